// round 1
// baseline (speedup 1.0000x reference)
#include <cuda_runtime.h>
#include <math.h>

// Problem capacities (fixed by the problem spec)
#define MAX_N 100000
#define MAX_E 600000

// Scratch (device globals: allocation-free rule)
// g_qu layout per node: [ q(128) | u_head0(128) | u_head1(128) ]  (384 floats)
__device__ float g_qu[(size_t)MAX_N * 384];
__device__ float g_k [(size_t)MAX_N * 128];
__device__ float g_v [(size_t)MAX_N * 128];
__device__ float g_A [(size_t)MAX_N * 256];   // attn-weighted edge_attr accumulator, per head
__device__ float g_ex[(size_t)MAX_E * 2];     // exp(alpha) per edge/head
__device__ float g_den[(size_t)MAX_N * 2];    // softmax denominators
__device__ float g_WeT[128 * 128];            // We transposed

// ---------------------------------------------------------------------------
// Generic fp32 SGEMM: C[M x Ncols] = A[M x K] @ B[K x Ncols] (+bias) (+=C)
// BM=128, BN=128(max), BK=8, 256 threads, 8x8 per-thread microtile.
// ---------------------------------------------------------------------------
__global__ __launch_bounds__(256) void sgemm128(
    const float* __restrict__ A, int lda,
    const float* __restrict__ B, int ldb,
    float* __restrict__ C, int ldc,
    int M, int Ncols, int K,
    const float* __restrict__ bias, int accum)
{
    __shared__ float As[8][128];
    __shared__ float Bs[8][128];
    int tid = threadIdx.x;
    int tx = tid & 15, ty = tid >> 4;
    int bm0 = blockIdx.x * 128;

    float acc[8][8];
#pragma unroll
    for (int i = 0; i < 8; i++)
#pragma unroll
        for (int j = 0; j < 8; j++) acc[i][j] = 0.f;

    int arow = tid >> 1;            // 0..127
    int acol = (tid & 1) * 4;       // 0 or 4
    int brow = tid >> 5;            // 0..7
    int bcol = (tid & 31) * 4;      // 0..124

    for (int k0 = 0; k0 < K; k0 += 8) {
        float4 av = make_float4(0.f, 0.f, 0.f, 0.f);
        if (bm0 + arow < M)
            av = *(const float4*)&A[(size_t)(bm0 + arow) * lda + k0 + acol];
        As[acol + 0][arow] = av.x;
        As[acol + 1][arow] = av.y;
        As[acol + 2][arow] = av.z;
        As[acol + 3][arow] = av.w;

        float4 bv = make_float4(0.f, 0.f, 0.f, 0.f);
        if (bcol < Ncols)
            bv = *(const float4*)&B[(size_t)(k0 + brow) * ldb + bcol];
        *(float4*)&Bs[brow][bcol] = bv;
        __syncthreads();

#pragma unroll
        for (int kk = 0; kk < 8; kk++) {
            float a[8], b[8];
            *(float4*)&a[0] = *(float4*)&As[kk][ty * 8];
            *(float4*)&a[4] = *(float4*)&As[kk][ty * 8 + 4];
            *(float4*)&b[0] = *(float4*)&Bs[kk][tx * 8];
            *(float4*)&b[4] = *(float4*)&Bs[kk][tx * 8 + 4];
#pragma unroll
            for (int i = 0; i < 8; i++)
#pragma unroll
                for (int j = 0; j < 8; j++)
                    acc[i][j] = fmaf(a[i], b[j], acc[i][j]);
        }
        __syncthreads();
    }

#pragma unroll
    for (int i = 0; i < 8; i++) {
        int row = bm0 + ty * 8 + i;
        if (row >= M) break;
#pragma unroll
        for (int j = 0; j < 8; j += 4) {
            int col = tx * 8 + j;
            if (col >= Ncols) continue;
            float4 v;
            v.x = acc[i][j + 0]; v.y = acc[i][j + 1];
            v.z = acc[i][j + 2]; v.w = acc[i][j + 3];
            if (bias) {
                v.x += bias[col + 0]; v.y += bias[col + 1];
                v.z += bias[col + 2]; v.w += bias[col + 3];
            }
            float* cp = &C[(size_t)row * ldc + col];
            if (accum) {
                float4 o = *(float4*)cp;
                v.x += o.x; v.y += o.y; v.z += o.z; v.w += o.w;
            }
            *(float4*)cp = v;
        }
    }
}

__global__ __launch_bounds__(256) void transpose_k(
    const float* __restrict__ W, float* __restrict__ WT)
{
    int t = blockIdx.x * 256 + threadIdx.x;   // 16384 total
    int r = t >> 7, c = t & 127;
    WT[c * 128 + r] = W[t];
}

// ---------------------------------------------------------------------------
// Edge kernels (1 warp per edge)
// ---------------------------------------------------------------------------
__device__ __forceinline__ float cos_acc(float x) {
    // Exact range reduction in double (args can reach +-4000), then cosf.
    float k = rintf(x * 0.15915494309189535f);
    float r = (float)((double)x - (double)k * 6.283185307179586);
    return cosf(r);
}

__device__ __forceinline__ float wsum(float v) {
#pragma unroll
    for (int o = 16; o; o >>= 1) v += __shfl_xor_sync(0xffffffffu, v, o);
    return v;
}

__device__ __forceinline__ void red4(float* p, float x, float y, float z, float w) {
    asm volatile("red.global.add.v4.f32 [%0], {%1,%2,%3,%4};"
                 :: "l"(p), "f"(x), "f"(y), "f"(z), "f"(w) : "memory");
}

__device__ __forceinline__ float4 edge_attr4(int lane, float relt,
                                             const float* __restrict__ msg,
                                             const float* __restrict__ wt,
                                             const float* __restrict__ bt,
                                             size_t e)
{
    float4 ea;
    if (lane < 16) {
        float4 w4 = ((const float4*)wt)[lane];
        float4 b4 = ((const float4*)bt)[lane];
        ea.x = cos_acc(fmaf(relt, w4.x, b4.x));
        ea.y = cos_acc(fmaf(relt, w4.y, b4.y));
        ea.z = cos_acc(fmaf(relt, w4.z, b4.z));
        ea.w = cos_acc(fmaf(relt, w4.w, b4.w));
    } else {
        ea = ((const float4*)(msg + e * 64))[lane - 16];
    }
    return ea;
}

__global__ __launch_bounds__(256) void edge_alpha_k(
    const int* __restrict__ ei, const float* __restrict__ lu,
    const float* __restrict__ tt, const float* __restrict__ msg,
    const float* __restrict__ wt, const float* __restrict__ bt, int E)
{
    int e = (int)((blockIdx.x * 256 + threadIdx.x) >> 5);
    int lane = threadIdx.x & 31;
    if (e >= E) return;
    int src = ei[e];
    int dst = ei[E + e];
    float relt = lu[src] - tt[e];

    float4 ea = edge_attr4(lane, relt, msg, wt, bt, (size_t)e);

    const float4* qu = (const float4*)(g_qu + (size_t)dst * 384);
    float4 q4 = qu[lane];
    float4 u0 = qu[32 + lane];
    float4 u1 = qu[64 + lane];
    float4 k4 = ((const float4*)(g_k + (size_t)src * 128))[lane];

    float pqk = q4.x * k4.x + q4.y * k4.y + q4.z * k4.z + q4.w * k4.w;
    float pe0 = ea.x * u0.x + ea.y * u0.y + ea.z * u0.z + ea.w * u0.w;
    float pe1 = ea.x * u1.x + ea.y * u1.y + ea.z * u1.z + ea.w * u1.w;

    float qk0 = wsum(lane < 16 ? pqk : 0.f);
    float qk1 = wsum(lane < 16 ? 0.f : pqk);
    pe0 = wsum(pe0);
    pe1 = wsum(pe1);

    if (lane == 0) {
        float ex0 = expf((qk0 + pe0) * 0.125f);
        float ex1 = expf((qk1 + pe1) * 0.125f);
        g_ex[2 * (size_t)e + 0] = ex0;
        g_ex[2 * (size_t)e + 1] = ex1;
        atomicAdd(&g_den[2 * dst + 0], ex0);
        atomicAdd(&g_den[2 * dst + 1], ex1);
    }
}

__global__ __launch_bounds__(256) void edge_agg_k(
    const int* __restrict__ ei, const float* __restrict__ lu,
    const float* __restrict__ tt, const float* __restrict__ msg,
    const float* __restrict__ wt, const float* __restrict__ bt,
    float* __restrict__ out, int E)
{
    int e = (int)((blockIdx.x * 256 + threadIdx.x) >> 5);
    int lane = threadIdx.x & 31;
    if (e >= E) return;
    int src = ei[e];
    int dst = ei[E + e];
    float relt = lu[src] - tt[e];

    float4 ea = edge_attr4(lane, relt, msg, wt, bt, (size_t)e);

    float a0 = 0.f, a1 = 0.f;
    if (lane == 0) {
        float d0 = g_den[2 * dst + 0];
        float d1 = g_den[2 * dst + 1];
        a0 = g_ex[2 * (size_t)e + 0] / (d0 + 1e-16f);
        a1 = g_ex[2 * (size_t)e + 1] / (d1 + 1e-16f);
    }
    a0 = __shfl_sync(0xffffffffu, a0, 0);
    a1 = __shfl_sync(0xffffffffu, a1, 0);

    float4 v4 = ((const float4*)(g_v + (size_t)src * 128))[lane];
    float av = (lane < 16) ? a0 : a1;

    red4(out + (size_t)dst * 128 + lane * 4, av * v4.x, av * v4.y, av * v4.z, av * v4.w);
    red4(g_A + (size_t)dst * 256 + lane * 4,       a0 * ea.x, a0 * ea.y, a0 * ea.z, a0 * ea.w);
    red4(g_A + (size_t)dst * 256 + 128 + lane * 4, a1 * ea.x, a1 * ea.y, a1 * ea.z, a1 * ea.w);
}

// ---------------------------------------------------------------------------
extern "C" void kernel_launch(void* const* d_in, const int* in_sizes, int n_in,
                              void* d_out, int out_size)
{
    const float* x    = (const float*)d_in[0];
    const float* lu   = (const float*)d_in[1];
    const int*   ei   = (const int*)  d_in[2];
    const float* tt   = (const float*)d_in[3];
    const float* msg  = (const float*)d_in[4];
    const float* wt   = (const float*)d_in[5];
    const float* bt   = (const float*)d_in[6];
    const float* Wq   = (const float*)d_in[7];
    const float* bq   = (const float*)d_in[8];
    const float* Wk   = (const float*)d_in[9];
    const float* bk   = (const float*)d_in[10];
    const float* Wv   = (const float*)d_in[11];
    const float* bv   = (const float*)d_in[12];
    const float* We   = (const float*)d_in[13];
    const float* Ws   = (const float*)d_in[14];
    const float* bs   = (const float*)d_in[15];
    float* out = (float*)d_out;

    int N = in_sizes[1];   // last_update length
    int E = in_sizes[3];   // t length

    float *pqu, *pk, *pv, *pA, *pden, *pWeT;
    cudaGetSymbolAddress((void**)&pqu,  g_qu);
    cudaGetSymbolAddress((void**)&pk,   g_k);
    cudaGetSymbolAddress((void**)&pv,   g_v);
    cudaGetSymbolAddress((void**)&pA,   g_A);
    cudaGetSymbolAddress((void**)&pden, g_den);
    cudaGetSymbolAddress((void**)&pWeT, g_WeT);

    cudaMemsetAsync(pden, 0, (size_t)N * 2   * sizeof(float));
    cudaMemsetAsync(pA,   0, (size_t)N * 256 * sizeof(float));

    transpose_k<<<64, 256>>>(We, pWeT);

    int gm = (N + 127) / 128;
    // projections: q -> g_qu[:,0:128], k, v, skip -> out
    sgemm128<<<gm, 256>>>(x, 128, Wq, 128, pqu, 384, N, 128, 128, bq, 0);
    sgemm128<<<gm, 256>>>(x, 128, Wk, 128, pk,  128, N, 128, 128, bk, 0);
    sgemm128<<<gm, 256>>>(x, 128, Wv, 128, pv,  128, N, 128, 128, bv, 0);
    sgemm128<<<gm, 256>>>(x, 128, Ws, 128, out, 128, N, 128, 128, bs, 0);
    // u[n,h,:] = We_h @ q[n,h,:]  via  q_h (Nx64) @ WeT rows [64h:64h+64) (64x128)
    sgemm128<<<gm, 256>>>(pqu,      384, pWeT,            128, pqu + 128, 384, N, 128, 64, nullptr, 0);
    sgemm128<<<gm, 256>>>(pqu + 64, 384, pWeT + 64 * 128, 128, pqu + 256, 384, N, 128, 64, nullptr, 0);

    int eb = (E + 7) / 8;   // 8 edges (warps) per 256-thread block
    edge_alpha_k<<<eb, 256>>>(ei, lu, tt, msg, wt, bt, E);
    edge_agg_k  <<<eb, 256>>>(ei, lu, tt, msg, wt, bt, out, E);

    // epilogue: out[:, 64h:64h+64) += A[:,h,:] (Nx128) @ We[:, 64h:64h+64)
    sgemm128<<<gm, 256>>>(pA,       256, We,      128, out,      128, N, 64, 128, nullptr, 1);
    sgemm128<<<gm, 256>>>(pA + 128, 256, We + 64, 128, out + 64, 128, N, 64, 128, nullptr, 1);
}

// round 2
// speedup vs baseline: 2.3406x; 2.3406x over previous
#include <cuda_runtime.h>
#include <math.h>

#define MAX_N 100000
#define MAX_E 600000

// Node record Y: [q(128) | u0(128) | u1(128) | k(128) | v(128) | skip(128)] = 768 floats
__device__ float g_Y  [(size_t)MAX_N * 768];
// Accumulators: [v_acc(128) | e_acc0(128) | e_acc1(128)] = 384 floats
__device__ float g_acc[(size_t)MAX_N * 384];
__device__ float g_den[(size_t)MAX_N * 2];
__device__ float g_Bcat[128 * 768];
__device__ float g_bcat[768];
__device__ float g_Bblk[256 * 128];

// ---------------------------------------------------------------------------
// SGEMM v2: C[M x (128*gridDim.y)] = A[M x K] @ B  (+bias) (+=C)
// 128 threads, BM=128, BN=128, BK=16, 16x8 microtile, cp.async double buffer.
// ---------------------------------------------------------------------------
__device__ __forceinline__ void cp16(unsigned dst, const void* src) {
    asm volatile("cp.async.cg.shared.global [%0], [%1], 16;" :: "r"(dst), "l"(src));
}

__global__ __launch_bounds__(128) void sgemm_v2(
    const float* __restrict__ A, int lda,
    const float* __restrict__ B, int ldb,
    float* __restrict__ C, int ldc,
    int M, int K,
    const float* __restrict__ bias, int accum)
{
    __shared__ float As[2][16][132];
    __shared__ float Bs[2][16][128];
    const int tid = threadIdx.x;
    const int tx = tid & 15, ty = tid >> 4;
    const int bm0 = blockIdx.x * 128;
    const int bn0 = blockIdx.y * 128;

    float acc[16][8];
#pragma unroll
    for (int i = 0; i < 16; i++)
#pragma unroll
        for (int j = 0; j < 8; j++) acc[i][j] = 0.f;

    float4 areg[4];
    const int ntiles = K >> 4;

    // ---- helpers as lambdas ----
    auto ldgA = [&](int kt) {
#pragma unroll
        for (int i = 0; i < 4; i++) {
            int fidx = tid + 128 * i;
            int row = bm0 + (fidx >> 2);
            int c = kt * 16 + (fidx & 3) * 4;
            areg[i] = (row < M) ? *(const float4*)&A[(size_t)row * lda + c]
                                : make_float4(0.f, 0.f, 0.f, 0.f);
        }
    };
    auto stsA = [&](int buf) {
#pragma unroll
        for (int i = 0; i < 4; i++) {
            int fidx = tid + 128 * i;
            int row = fidx >> 2;
            int c = (fidx & 3) * 4;
            As[buf][c + 0][row] = areg[i].x;
            As[buf][c + 1][row] = areg[i].y;
            As[buf][c + 2][row] = areg[i].z;
            As[buf][c + 3][row] = areg[i].w;
        }
    };
    auto cpB = [&](int kt, int buf) {
#pragma unroll
        for (int i = 0; i < 4; i++) {
            int idx = tid + 128 * i;
            int row = idx >> 5;
            int c4 = (idx & 31) * 4;
            unsigned dst = (unsigned)__cvta_generic_to_shared(&Bs[buf][row][c4]);
            cp16(dst, &B[(size_t)(kt * 16 + row) * ldb + bn0 + c4]);
        }
        asm volatile("cp.async.commit_group;");
    };

    // prologue: tile 0 -> buffer 0
    ldgA(0);
    stsA(0);
    cpB(0, 0);
    asm volatile("cp.async.wait_group 0;");
    __syncthreads();

    for (int t = 0; t < ntiles; t++) {
        int cur = t & 1, nxt = cur ^ 1;
        bool more = (t + 1 < ntiles);
        if (more) {
            ldgA(t + 1);
            cpB(t + 1, nxt);
        }
#pragma unroll
        for (int kk = 0; kk < 16; kk++) {
            float a[16], b[8];
            *(float4*)&a[0]  = *(const float4*)&As[cur][kk][ty * 16 + 0];
            *(float4*)&a[4]  = *(const float4*)&As[cur][kk][ty * 16 + 4];
            *(float4*)&a[8]  = *(const float4*)&As[cur][kk][ty * 16 + 8];
            *(float4*)&a[12] = *(const float4*)&As[cur][kk][ty * 16 + 12];
#pragma unroll
            for (int j = 0; j < 8; j++) b[j] = Bs[cur][kk][tx + 16 * j];
#pragma unroll
            for (int i = 0; i < 16; i++)
#pragma unroll
                for (int j = 0; j < 8; j++)
                    acc[i][j] = fmaf(a[i], b[j], acc[i][j]);
        }
        if (more) {
            stsA(nxt);
            asm volatile("cp.async.wait_group 0;");
        }
        __syncthreads();
    }

#pragma unroll
    for (int i = 0; i < 16; i++) {
        int row = bm0 + ty * 16 + i;
        if (row >= M) break;
#pragma unroll
        for (int j = 0; j < 8; j++) {
            int col = bn0 + tx + 16 * j;
            float v = acc[i][j];
            if (bias) v += bias[col];
            float* cp = &C[(size_t)row * ldc + col];
            if (accum) v += *cp;
            *cp = v;
        }
    }
}

// ---------------------------------------------------------------------------
// Prep kernels (tiny)
// ---------------------------------------------------------------------------
__global__ __launch_bounds__(128) void prep_bcat(
    const float* __restrict__ Wq, const float* __restrict__ bq,
    const float* __restrict__ Wk, const float* __restrict__ bk,
    const float* __restrict__ Wv, const float* __restrict__ bv,
    const float* __restrict__ Ws, const float* __restrict__ bs,
    const float* __restrict__ We)
{
    int j = blockIdx.x;      // 0..767
    int r = threadIdx.x;     // 0..127
    float v;
    if (j < 128) v = Wq[r * 128 + j];
    else if (j < 256) {
        int d = j - 128; const float* w = We + d * 128;
        float s = 0.f;
#pragma unroll
        for (int c = 0; c < 64; c++) s = fmaf(Wq[r * 128 + c], w[c], s);
        v = s;
    } else if (j < 384) {
        int d = j - 256; const float* w = We + d * 128 + 64;
        float s = 0.f;
#pragma unroll
        for (int c = 0; c < 64; c++) s = fmaf(Wq[r * 128 + 64 + c], w[c], s);
        v = s;
    }
    else if (j < 512) v = Wk[r * 128 + (j - 384)];
    else if (j < 640) v = Wv[r * 128 + (j - 512)];
    else              v = Ws[r * 128 + (j - 640)];
    g_Bcat[r * 768 + j] = v;

    if (r == 0) {
        float bv2;
        if (j < 128) bv2 = bq[j];
        else if (j < 256) {
            int d = j - 128; const float* w = We + d * 128;
            float s = 0.f;
            for (int c = 0; c < 64; c++) s = fmaf(bq[c], w[c], s);
            bv2 = s;
        } else if (j < 384) {
            int d = j - 256; const float* w = We + d * 128 + 64;
            float s = 0.f;
            for (int c = 0; c < 64; c++) s = fmaf(bq[64 + c], w[c], s);
            bv2 = s;
        }
        else if (j < 512) bv2 = bk[j - 384];
        else if (j < 640) bv2 = bv[j - 512];
        else              bv2 = bs[j - 640];
        g_bcat[j] = bv2;
    }
}

__global__ __launch_bounds__(256) void prep_bblk(const float* __restrict__ We)
{
    int n = blockIdx.x;      // 0..127
    int k = threadIdx.x;     // 0..255
    float v = 0.f;
    if (k < 128) { if (n < 64)  v = We[k * 128 + n]; }
    else         { if (n >= 64) v = We[(k - 128) * 128 + n]; }
    g_Bblk[k * 128 + n] = v;
}

// ---------------------------------------------------------------------------
// Fused edge pass (1 warp per edge)
// ---------------------------------------------------------------------------
__device__ __forceinline__ float cos_acc(float x) {
    float k = rintf(x * 0.15915494309189535f);
    float r = (float)((double)x - (double)k * 6.283185307179586);
    return cosf(r);
}
__device__ __forceinline__ float wsum(float v) {
#pragma unroll
    for (int o = 16; o; o >>= 1) v += __shfl_xor_sync(0xffffffffu, v, o);
    return v;
}
__device__ __forceinline__ void red4(float* p, float x, float y, float z, float w) {
    asm volatile("red.global.add.v4.f32 [%0], {%1,%2,%3,%4};"
                 :: "l"(p), "f"(x), "f"(y), "f"(z), "f"(w) : "memory");
}

__global__ __launch_bounds__(256) void edge_fused_k(
    const int* __restrict__ ei, const float* __restrict__ lu,
    const float* __restrict__ tt, const float* __restrict__ msg,
    const float* __restrict__ wt, const float* __restrict__ bt, int E)
{
    int e = (int)((blockIdx.x * 256 + threadIdx.x) >> 5);
    int lane = threadIdx.x & 31;
    if (e >= E) return;
    int src = ei[e];
    int dst = ei[E + e];
    float relt = lu[src] - tt[e];

    // edge_attr: lanes 0-15 time enc (cos), lanes 16-31 msg
    float4 ea;
    if (lane < 16) {
        float4 w4 = ((const float4*)wt)[lane];
        float4 b4 = ((const float4*)bt)[lane];
        ea.x = cos_acc(fmaf(relt, w4.x, b4.x));
        ea.y = cos_acc(fmaf(relt, w4.y, b4.y));
        ea.z = cos_acc(fmaf(relt, w4.z, b4.z));
        ea.w = cos_acc(fmaf(relt, w4.w, b4.w));
    } else {
        ea = ((const float4*)(msg + (size_t)e * 64))[lane - 16];
    }

    const float4* Yd = (const float4*)(g_Y + (size_t)dst * 768);
    const float4* Ys = (const float4*)(g_Y + (size_t)src * 768);
    float4 q4 = Yd[lane];
    float4 u0 = Yd[32 + lane];
    float4 u1 = Yd[64 + lane];
    float4 k4 = Ys[96 + lane];
    float4 v4 = Ys[128 + lane];

    float pqk = q4.x * k4.x + q4.y * k4.y + q4.z * k4.z + q4.w * k4.w;
    float pe0 = ea.x * u0.x + ea.y * u0.y + ea.z * u0.z + ea.w * u0.w;
    float pe1 = ea.x * u1.x + ea.y * u1.y + ea.z * u1.z + ea.w * u1.w;

    float qk0 = wsum(lane < 16 ? pqk : 0.f);
    float qk1 = wsum(lane < 16 ? 0.f : pqk);
    pe0 = wsum(pe0);
    pe1 = wsum(pe1);

    float ex0 = expf((qk0 + pe0) * 0.125f);
    float ex1 = expf((qk1 + pe1) * 0.125f);

    if (lane == 0) {
        atomicAdd(&g_den[2 * dst + 0], ex0);
        atomicAdd(&g_den[2 * dst + 1], ex1);
    }

    float* accn = g_acc + (size_t)dst * 384;
    float av = (lane < 16) ? ex0 : ex1;   // v cols 0..63 head0, 64..127 head1
    red4(accn + lane * 4,       av * v4.x, av * v4.y, av * v4.z, av * v4.w);
    red4(accn + 128 + lane * 4, ex0 * ea.x, ex0 * ea.y, ex0 * ea.z, ex0 * ea.w);
    red4(accn + 256 + lane * 4, ex1 * ea.x, ex1 * ea.y, ex1 * ea.z, ex1 * ea.w);
}

// ---------------------------------------------------------------------------
// Final normalize: out = skip + acc_v / den
// ---------------------------------------------------------------------------
__global__ __launch_bounds__(256) void normalize_k(float* __restrict__ out, int N)
{
    int idx = blockIdx.x * 256 + threadIdx.x;   // over N*32 float4s
    if (idx >= N * 32) return;
    int n = idx >> 5, c4 = idx & 31;
    float4 sk = ((const float4*)(g_Y + (size_t)n * 768 + 640))[c4];
    float4 av = ((const float4*)(g_acc + (size_t)n * 384))[c4];
    float d = g_den[2 * n + (c4 >> 4)] + 1e-16f;
    float inv = 1.f / d;
    float4 o;
    o.x = sk.x + av.x * inv;
    o.y = sk.y + av.y * inv;
    o.z = sk.z + av.z * inv;
    o.w = sk.w + av.w * inv;
    ((float4*)out)[idx] = o;
}

// ---------------------------------------------------------------------------
extern "C" void kernel_launch(void* const* d_in, const int* in_sizes, int n_in,
                              void* d_out, int out_size)
{
    const float* x    = (const float*)d_in[0];
    const float* lu   = (const float*)d_in[1];
    const int*   ei   = (const int*)  d_in[2];
    const float* tt   = (const float*)d_in[3];
    const float* msg  = (const float*)d_in[4];
    const float* wt   = (const float*)d_in[5];
    const float* bt   = (const float*)d_in[6];
    const float* Wq   = (const float*)d_in[7];
    const float* bq   = (const float*)d_in[8];
    const float* Wk   = (const float*)d_in[9];
    const float* bk   = (const float*)d_in[10];
    const float* Wv   = (const float*)d_in[11];
    const float* bv   = (const float*)d_in[12];
    const float* We   = (const float*)d_in[13];
    const float* Ws   = (const float*)d_in[14];
    const float* bs   = (const float*)d_in[15];
    float* out = (float*)d_out;

    int N = in_sizes[1];
    int E = in_sizes[3];

    float *pY, *pacc, *pden, *pBcat, *pbcat, *pBblk;
    cudaGetSymbolAddress((void**)&pY,    g_Y);
    cudaGetSymbolAddress((void**)&pacc,  g_acc);
    cudaGetSymbolAddress((void**)&pden,  g_den);
    cudaGetSymbolAddress((void**)&pBcat, g_Bcat);
    cudaGetSymbolAddress((void**)&pbcat, g_bcat);
    cudaGetSymbolAddress((void**)&pBblk, g_Bblk);

    cudaMemsetAsync(pden, 0, (size_t)N * 2   * sizeof(float));
    cudaMemsetAsync(pacc, 0, (size_t)N * 384 * sizeof(float));

    prep_bcat<<<768, 128>>>(Wq, bq, Wk, bk, Wv, bv, Ws, bs, We);
    prep_bblk<<<128, 256>>>(We);

    int gm = (N + 127) / 128;

    // One wide projection GEMM: Y[N x 768] = x @ Bcat + bcat
    sgemm_v2<<<dim3(gm, 6), 128>>>(x, 128, pBcat, 768, pY, 768, N, 128, pbcat, 0);

    // Single fused edge pass
    edge_fused_k<<<(E + 7) / 8, 256>>>(ei, lu, tt, msg, wt, bt, E);

    // Epilogue GEMM: acc_v += acc_e[N x 256] @ Bblk[256 x 128]
    sgemm_v2<<<dim3(gm, 1), 128>>>(pacc + 128, 384, pBblk, 128, pacc, 384, N, 256, nullptr, 1);

    // out = skip + acc_v / den
    normalize_k<<<(N * 32 + 255) / 256, 256>>>(out, N);
}